// round 11
// baseline (speedup 1.0000x reference)
#include <cuda_runtime.h>
#include <cuda_bf16.h>
#include <cstdint>

#define NN 8192
#define DIN 256
#define DOUT 32
#define NPART 256            // pool partial blocks (32 rows)
#define NCH 64               // gemm2 chunks (128 k each: 96 MMA + 32 FFMA)

__device__ __align__(16) __nv_bfloat16 g_Bhi[DOUT * NN];   // support hi, n-major
__device__ __align__(16) __nv_bfloat16 g_Blo[DOUT * NN];   // support lo
__device__ __align__(16) float g_supF[NN * DOUT];          // support fp32, node-major
__device__ float    g_logits[NN * DOUT];
__device__ unsigned g_colmax_bits[DOUT];
__device__ float    g_sumpart[NPART * DOUT];
__device__ float    g_part[NPART * DOUT * DIN];

// ---------------- helpers ----------------
__device__ __forceinline__ unsigned long long pack2(float x) {
    unsigned long long r; asm("mov.b64 %0, {%1, %1};" : "=l"(r) : "f"(x)); return r;
}
__device__ __forceinline__ unsigned long long ffma2(unsigned long long a,
                                                    unsigned long long b,
                                                    unsigned long long c) {
    unsigned long long d;
    asm("fma.rn.f32x2 %0, %1, %2, %3;" : "=l"(d) : "l"(a), "l"(b), "l"(c));
    return d;
}
__device__ __forceinline__ float2 unpack2(unsigned long long v) {
    float2 f; asm("mov.b64 {%0, %1}, %2;" : "=f"(f.x), "=f"(f.y) : "l"(v)); return f;
}
__device__ __forceinline__ unsigned fkey(float f) {
    int b = __float_as_int(f);
    return (unsigned)(b ^ ((b >> 31) | 0x80000000));
}
__device__ __forceinline__ float funkey(unsigned u) {
    int b = (u & 0x80000000u) ? (int)(u ^ 0x80000000u) : ~(int)u;
    return __int_as_float(b);
}
__device__ __forceinline__ void split2t(float2 v, uint32_t& hi, uint32_t& lo) {
    uint32_t u0 = __float_as_uint(v.x), u1 = __float_as_uint(v.y);
    asm("prmt.b32 %0, %1, %2, 0x7632;" : "=r"(hi) : "r"(u0), "r"(u1));
    float l0 = v.x - __uint_as_float(u0 & 0xFFFF0000u);
    float l1 = v.y - __uint_as_float(u1 & 0xFFFF0000u);
    asm("cvt.rn.bf16x2.f32 %0, %1, %2;" : "=r"(lo) : "f"(l1), "f"(l0));
}
__device__ __forceinline__ uint32_t smem_u32(const void* p) {
    uint32_t a;
    asm("{ .reg .u64 t; cvta.to.shared.u64 t, %1; cvt.u32.u64 %0, t; }"
        : "=r"(a) : "l"(p));
    return a;
}
__device__ __forceinline__ void mma_bf16(float& c0, float& c1, float& c2, float& c3,
                                         uint32_t a0, uint32_t a1, uint32_t a2,
                                         uint32_t a3, uint32_t b0, uint32_t b1) {
    asm volatile(
        "mma.sync.aligned.m16n8k16.row.col.f32.bf16.bf16.f32 "
        "{%0,%1,%2,%3}, {%4,%5,%6,%7}, {%8,%9}, {%0,%1,%2,%3};"
        : "+f"(c0), "+f"(c1), "+f"(c2), "+f"(c3)
        : "r"(a0), "r"(a1), "r"(a2), "r"(a3), "r"(b0), "r"(b1));
}
#define CP16(sm, gp) asm volatile( \
    "cp.async.cg.shared.global [%0], [%1], 16;" :: "r"(sm), "l"(gp) : "memory")
#define CP4(sm, gp) asm volatile( \
    "cp.async.ca.shared.global [%0], [%1], 4;" :: "r"(sm), "l"(gp) : "memory")
#define CP_COMMIT() asm volatile("cp.async.commit_group;" ::: "memory")
#define CP_WAIT2()  asm volatile("cp.async.wait_group 2;" ::: "memory")

// ---------------------------------------------------------------------------
// gemm2 hybrid: logits = A @ support.
//  Tensor path: k in [0,6144), bf16 3-term, 8 warps (4 m16-tiles x 2 k-slices
//  of 48k). FFMA2 path: k in [6144,8192), exact fp32, 4 warps (4 x 8k slices,
//  2 rows/lane, round-1 inner loop). Both pipes run concurrently per chunk.
//  128 CTAs x 64 rows, 384 threads, cp.async 4-deep ring.
// Buffer layout (uint32 words):
//   A_MMA  [64r][100]         @0      (6400)   fp32, 96k + pad
//   A_FFMA [32k][66]          @6400   (2112)   fp32 TRANSPOSED via cp4
//   B_hi   [2 s2][32n][28]    @8512   (1792)
//   B_lo                      @10304  (1792)
//   B_f32  [32k][36]          @12096  (1152)
// ---------------------------------------------------------------------------
#define AM_OFF 0
#define AF_OFF 6400
#define BH_OFF 8512
#define BL_OFF 10304
#define BF_OFF 12096
#define BUFW   13248
#define RING 4
#define GEMM2_SMEM (RING * BUFW * 4)    // 211968 B

__global__ void __launch_bounds__(384, 1)
gemm2_kernel(const float* __restrict__ A)
{
    extern __shared__ uint32_t smu[];
    __shared__ unsigned smax[DOUT];
    const int t = threadIdx.x;            // 0..383
    const int w = t >> 5, lane = t & 31;
    const int gid = lane >> 2, t4 = lane & 3;
    const int rb = blockIdx.x * 64;
    const uint32_t smaddr = smem_u32(smu);

    if (t < DOUT) smax[t] = 0u;

    // ---- cp.async descriptors ----
    // A_MMA: 1536 cp16, 4 per thread. row = f/24, seg = f%24.
    const float* gAM[4]; uint32_t sAM[4];
#pragma unroll
    for (int j = 0; j < 4; j++) {
        int f = t + j * 384;
        int row = f / 24, seg = f % 24;
        gAM[j] = A + (size_t)(rb + row) * NN + seg * 4;          // +ch*96
        sAM[j] = smaddr + 4u * (AM_OFF + row * 100 + seg * 4);
    }
    // Bhi/Blo: 384 cp16 each, 1 per thread. s2 = t/192, n = (t%192)/6, cs = t%6
    const __nv_bfloat16 *gBH, *gBL; uint32_t sBH, sBL;
    {
        int s2 = t / 192, n = (t % 192) / 6, cs = t % 6;
        gBH = g_Bhi + (size_t)n * NN + s2 * 48 + cs * 8;          // +ch*96
        gBL = g_Blo + (size_t)n * NN + s2 * 48 + cs * 8;
        uint32_t off = (uint32_t)((s2 * 32 + n) * 28 + cs * 4);
        sBH = smaddr + 4u * (BH_OFF + off);
        sBL = smaddr + 4u * (BL_OFF + off);
    }
    // Bf32: 256 cp16, t<256. k = t/8, seg = t%8
    const float* gBF = nullptr; uint32_t sBF = 0;
    if (t < 256) {
        int k = t >> 3, seg = t & 7;
        gBF = g_supF + (size_t)(6144 + k) * DOUT + seg * 4;       // +ch*32*32
        sBF = smaddr + 4u * (BF_OFF + k * 36 + seg * 4);
    }
    // A_FFMA: 2048 cp4 (transpose!), 5 per thread + extra for t<128.
    const float* gAF[6]; uint32_t sAF[6];
#pragma unroll
    for (int j = 0; j < 6; j++) {
        int f = t + j * 384;
        if (f < 2048) {
            int r = f >> 5, k = f & 31;
            gAF[j] = A + (size_t)(rb + r) * NN + 6144 + k;        // +ch*32
            sAF[j] = smaddr + 4u * (AF_OFF + k * 66 + r);
        } else { gAF[j] = nullptr; sAF[j] = 0; }
    }

    // MMA accumulators (only meaningful for w<8); FFMA accs for w>=8
    float acc[4][4];
    unsigned long long fac0[16], fac1[16];
#pragma unroll
    for (int j = 0; j < 4; j++)
#pragma unroll
        for (int i = 0; i < 4; i++) acc[j][i] = 0.0f;
#pragma unroll
    for (int i = 0; i < 16; i++) { fac0[i] = 0ull; fac1[i] = 0ull; }

    // ---- issue one chunk's copies ----
    auto issue = [&](int c) {
        uint32_t bo = (uint32_t)(c & 3) * (BUFW * 4);
#pragma unroll
        for (int j = 0; j < 4; j++) CP16(sAM[j] + bo, gAM[j] + c * 96);
        CP16(sBH + bo, gBH + c * 96);
        CP16(sBL + bo, gBL + c * 96);
        if (t < 256) CP16(sBF + bo, gBF + c * 1024);
#pragma unroll
        for (int j = 0; j < 6; j++)
            if (gAF[j]) CP4(sAF[j] + bo, gAF[j] + c * 32);
    };

#pragma unroll
    for (int p = 0; p < 3; p++) { issue(p); CP_COMMIT(); }

    const int m0 = (w & 3) * 16, s2 = w >> 2;   // MMA decode (w<8)
    const int fw = w - 8;                        // FFMA decode (w>=8)

    for (int ch = 0; ch < NCH; ch++) {
        CP_WAIT2();
        __syncthreads();
        if (ch + 3 < NCH) issue(ch + 3);
        CP_COMMIT();

        const uint32_t* sb = smu + (ch & 3) * BUFW;
        const float* sbf = (const float*)sb;

        if (w < 8) {
            // ---- tensor path: 3 s-values of k16 within this warp's 48k ----
#pragma unroll
            for (int s = 0; s < 3; s++) {
                const int ab = AM_OFF + s2 * 48 + s * 16 + 2 * t4;
                float2 v00 = *reinterpret_cast<const float2*>(sbf + ab + (m0 + gid) * 100);
                float2 v10 = *reinterpret_cast<const float2*>(sbf + ab + (m0 + gid + 8) * 100);
                float2 v01 = *reinterpret_cast<const float2*>(sbf + ab + 8 + (m0 + gid) * 100);
                float2 v11 = *reinterpret_cast<const float2*>(sbf + ab + 8 + (m0 + gid + 8) * 100);
                uint32_t ah0, ah1, ah2, ah3, al0, al1, al2, al3;
                split2t(v00, ah0, al0);
                split2t(v10, ah1, al1);
                split2t(v01, ah2, al2);
                split2t(v11, ah3, al3);
#pragma unroll
                for (int j = 0; j < 4; j++) {
                    const int bx = BH_OFF + s2 * 896 + (gid + 8 * j) * 28 + s * 8 + t4;
                    uint32_t bh0 = sb[bx], bh1 = sb[bx + 4];
                    uint32_t bl0 = sb[bx + (BL_OFF - BH_OFF)];
                    uint32_t bl1 = sb[bx + (BL_OFF - BH_OFF) + 4];
                    mma_bf16(acc[j][0], acc[j][1], acc[j][2], acc[j][3],
                             ah0, ah1, ah2, ah3, bh0, bh1);
                    mma_bf16(acc[j][0], acc[j][1], acc[j][2], acc[j][3],
                             ah0, ah1, ah2, ah3, bl0, bl1);
                    mma_bf16(acc[j][0], acc[j][1], acc[j][2], acc[j][3],
                             al0, al1, al2, al3, bh0, bh1);
                }
            }
        } else {
            // ---- fp32 FFMA2 path: this warp's 8k slice, rows (lane, lane+32) ----
#pragma unroll
            for (int kk = 0; kk < 8; kk++) {
                const int k = fw * 8 + kk;
                unsigned long long a0 = pack2(sbf[AF_OFF + k * 66 + lane]);
                unsigned long long a1 = pack2(sbf[AF_OFF + k * 66 + lane + 32]);
                const ulonglong2* bv =
                    reinterpret_cast<const ulonglong2*>(sbf + BF_OFF + k * 36);
#pragma unroll
                for (int c = 0; c < 8; c++) {
                    ulonglong2 sv = bv[c];
                    fac0[2 * c]     = ffma2(a0, sv.x, fac0[2 * c]);
                    fac0[2 * c + 1] = ffma2(a0, sv.y, fac0[2 * c + 1]);
                    fac1[2 * c]     = ffma2(a1, sv.x, fac1[2 * c]);
                    fac1[2 * c + 1] = ffma2(a1, sv.y, fac1[2 * c + 1]);
                }
            }
        }
    }
    __syncthreads();

    // ---- epilogue: fixed-order merge of 6 partial sets ----
    // red sets: 0 = MMA s2=1 ; 1..4 = FFMA warps 0..3. Each [64][33].
    float* red = (float*)smu;
    if (w < 8 && s2 == 1) {
#pragma unroll
        for (int j = 0; j < 4; j++) {
            int r0 = m0 + gid, c = 8 * j + 2 * t4;
            red[r0 * 33 + c]           = acc[j][0];
            red[r0 * 33 + c + 1]       = acc[j][1];
            red[(r0 + 8) * 33 + c]     = acc[j][2];
            red[(r0 + 8) * 33 + c + 1] = acc[j][3];
        }
    }
    if (w >= 8) {
        float* rp = red + (fw + 1) * (64 * 33);
#pragma unroll
        for (int c = 0; c < 16; c++) {
            float2 v0 = unpack2(fac0[c]);
            float2 v1 = unpack2(fac1[c]);
            rp[lane * 33 + 2 * c]            = v0.x;
            rp[lane * 33 + 2 * c + 1]        = v0.y;
            rp[(lane + 32) * 33 + 2 * c]     = v1.x;
            rp[(lane + 32) * 33 + 2 * c + 1] = v1.y;
        }
    }
    __syncthreads();
    if (w < 8 && s2 == 0) {
#pragma unroll
        for (int j = 0; j < 4; j++) {
            int r0 = m0 + gid, c = 8 * j + 2 * t4;
            float v0 = acc[j][0], v1 = acc[j][1], v2 = acc[j][2], v3 = acc[j][3];
#pragma unroll
            for (int p = 0; p < 5; p++) {
                const float* rp = red + p * (64 * 33);
                v0 += rp[r0 * 33 + c];
                v1 += rp[r0 * 33 + c + 1];
                v2 += rp[(r0 + 8) * 33 + c];
                v3 += rp[(r0 + 8) * 33 + c + 1];
            }
            *reinterpret_cast<float2*>(&g_logits[(size_t)(rb + r0) * DOUT + c]) =
                make_float2(v0, v1);
            *reinterpret_cast<float2*>(&g_logits[(size_t)(rb + r0 + 8) * DOUT + c]) =
                make_float2(v2, v3);
            atomicMax(&smax[c],     fkey(fmaxf(v0, v2)));
            atomicMax(&smax[c + 1], fkey(fmaxf(v1, v3)));
        }
    }
    __syncthreads();
    if (t < DOUT) atomicMax(&g_colmax_bits[t], smax[t]);
}

// ---------------------------------------------------------------------------
// gemm1: support = X @ W -> bf16 hi/lo (n-major) + fp32 (node-major).
// ---------------------------------------------------------------------------
#define ABUF_STRIDE (32 * 65)
#define SBUF_BASE   (8 * ABUF_STRIDE)
#define GEMM1_SMEM  ((SBUF_BASE + 8 * 32 * 32) * 4)

__global__ void __launch_bounds__(256)
gemm1_kernel(const float* __restrict__ A, const float* __restrict__ S)
{
    extern __shared__ float smem[];
    const int t = threadIdx.x, w = t >> 5, l = t & 31;
    const int rb = blockIdx.x * 64;
    const int K = DIN;

    if (blockIdx.x == 0 && t < DOUT) g_colmax_bits[t] = 0u;

    float* a_buf = smem + w * ABUF_STRIDE;
    float* s_buf = smem + SBUF_BASE + w * (32 * 32);
    const int kc = w * 32;

    unsigned long long acc0[16], acc1[16];
#pragma unroll
    for (int i = 0; i < 16; i++) { acc0[i] = 0ull; acc1[i] = 0ull; }

#pragma unroll
    for (int j = 0; j < 16; j++) {
        int f = j * 32 + l, row = f >> 3, k4 = (f & 7) << 2;
        float4 v = *reinterpret_cast<const float4*>(
            A + (size_t)(rb + row) * K + kc + k4);
        a_buf[(k4 + 0) * 65 + row] = v.x;
        a_buf[(k4 + 1) * 65 + row] = v.y;
        a_buf[(k4 + 2) * 65 + row] = v.z;
        a_buf[(k4 + 3) * 65 + row] = v.w;
    }
#pragma unroll
    for (int j = 0; j < 8; j++) {
        int f = j * 32 + l;
        *reinterpret_cast<float4*>(s_buf + f * 4) =
            *reinterpret_cast<const float4*>(S + (size_t)kc * 32 + f * 4);
    }
    __syncwarp();
#pragma unroll 4
    for (int k = 0; k < 32; k++) {
        unsigned long long a0 = pack2(a_buf[k * 65 + l]);
        unsigned long long a1 = pack2(a_buf[k * 65 + l + 32]);
        const ulonglong2* s2 = reinterpret_cast<const ulonglong2*>(s_buf + k * 32);
#pragma unroll
        for (int c = 0; c < 8; c++) {
            ulonglong2 sv = s2[c];
            acc0[2 * c]     = ffma2(a0, sv.x, acc0[2 * c]);
            acc0[2 * c + 1] = ffma2(a0, sv.y, acc0[2 * c + 1]);
            acc1[2 * c]     = ffma2(a1, sv.x, acc1[2 * c]);
            acc1[2 * c + 1] = ffma2(a1, sv.y, acc1[2 * c + 1]);
        }
    }

    __syncthreads();
    float* red = smem;
#pragma unroll
    for (int c = 0; c < 16; c++) {
        float2 v0 = unpack2(acc0[c]);
        float2 v1 = unpack2(acc1[c]);
        red[(w * 64 + l) * 33 + 2 * c]          = v0.x;
        red[(w * 64 + l) * 33 + 2 * c + 1]      = v0.y;
        red[(w * 64 + l + 32) * 33 + 2 * c]     = v1.x;
        red[(w * 64 + l + 32) * 33 + 2 * c + 1] = v1.y;
    }
    __syncthreads();
    {
        int row = t >> 2, c0 = (t & 3) * 8;
        float r[8];
#pragma unroll
        for (int i = 0; i < 8; i++) r[i] = 0.0f;
#pragma unroll
        for (int ww = 0; ww < 8; ww++) {
            const float* p = red + (ww * 64 + row) * 33 + c0;
#pragma unroll
            for (int i = 0; i < 8; i++) r[i] += p[i];
        }
#pragma unroll
        for (int i = 0; i < 8; i++) {
            __nv_bfloat16 hi = __float2bfloat16(r[i]);
            g_Bhi[(size_t)(c0 + i) * NN + rb + row] = hi;
            g_Blo[(size_t)(c0 + i) * NN + rb + row] =
                __float2bfloat16(r[i] - __bfloat162float(hi));
            g_supF[(size_t)(rb + row) * DOUT + c0 + i] = r[i];
        }
    }
}

// ---------------- pool: 32-row x d-split, fused per-block exp sums ---------
__global__ void __launch_bounds__(128, 4)
pool_kernel(const float* __restrict__ X)
{
    __shared__ float wsm[32 * DOUT];
    __shared__ float cmax[DOUT];
    const int t   = threadIdx.x;              // 128
    const int blk = (int)blockIdx.x >> 1;     // 0..255
    const int dh  = (int)blockIdx.x & 1;
    const int rb  = blk * 32;
    const int d   = dh * 128 + t;

    if (t < DOUT) cmax[t] = funkey(g_colmax_bits[t]);
    __syncthreads();
#pragma unroll
    for (int q = 0; q < 8; q++) {
        int idx = t * 8 + q, il = idx >> 5, c = idx & 31;
        wsm[idx] = __expf(g_logits[(size_t)(rb + il) * DOUT + c] - cmax[c]);
    }
    __syncthreads();

    // fused expsum partial (one warp, conflict-free column sums)
    if (dh == 0 && t < DOUT) {
        float s = 0.f;
#pragma unroll 8
        for (int il = 0; il < 32; il++) s += wsm[il * DOUT + t];
        g_sumpart[blk * DOUT + t] = s;
    }

    unsigned long long acc[16];
#pragma unroll
    for (int i = 0; i < 16; i++) acc[i] = 0ull;
    for (int g = 0; g < 4; g++) {
        float xv[8];
#pragma unroll
        for (int q = 0; q < 8; q++)
            xv[q] = X[(size_t)(rb + g * 8 + q) * DIN + d];
#pragma unroll
        for (int q = 0; q < 8; q++) {
            unsigned long long xp = pack2(xv[q]);
            const ulonglong2* wv =
                reinterpret_cast<const ulonglong2*>(wsm + (g * 8 + q) * DOUT);
#pragma unroll
            for (int c = 0; c < 8; c++) {
                ulonglong2 sv = wv[c];
                acc[2 * c]     = ffma2(xp, sv.x, acc[2 * c]);
                acc[2 * c + 1] = ffma2(xp, sv.y, acc[2 * c + 1]);
            }
        }
    }
    float* pp = g_part + (size_t)blk * (DOUT * DIN);
#pragma unroll
    for (int c = 0; c < 16; c++) {
        float2 v = unpack2(acc[c]);
        pp[(2 * c) * DIN + d]     = v.x;
        pp[(2 * c + 1) * DIN + d] = v.y;
    }
}

// ---------------- final reduce + normalize ---------------------------------
__global__ void reduce_out_kernel(float* __restrict__ out)
{
    __shared__ float sred[NPART];
    const int c = blockIdx.x, t = threadIdx.x;   // 32 blocks x 256 thr
    sred[t] = g_sumpart[t * DOUT + c];
    __syncthreads();
    for (int s = 128; s > 0; s >>= 1) {
        if (t < s) sred[t] += sred[t + s];
        __syncthreads();
    }
    const float inv = 1.0f / sred[0];
    float s = 0.0f;
#pragma unroll 8
    for (int b = 0; b < NPART; b++)
        s += g_part[(size_t)b * (DOUT * DIN) + c * DIN + t];
    out[c * DIN + t] = s * inv;
}

extern "C" void kernel_launch(void* const* d_in, const int* in_sizes, int n_in,
                              void* d_out, int out_size)
{
    const float* X = (const float*)d_in[0];
    const float* A = (const float*)d_in[1];
    const float* W = (const float*)d_in[2];
    // d_in[3] = b: per-column constant -> softmax(axis 0) invariant -> dropped
    float* out = (float*)d_out;

    cudaFuncSetAttribute(gemm1_kernel,
                         cudaFuncAttributeMaxDynamicSharedMemorySize, GEMM1_SMEM);
    cudaFuncSetAttribute(gemm2_kernel,
                         cudaFuncAttributeMaxDynamicSharedMemorySize, GEMM2_SMEM);

    gemm1_kernel<<<NN / 64, 256, GEMM1_SMEM>>>(X, W);
    gemm2_kernel<<<NN / 64, 384, GEMM2_SMEM>>>(A);
    pool_kernel<<<NPART * 2, 128>>>(X);
    reduce_out_kernel<<<DOUT, 256>>>(out);
}

// round 12
// speedup vs baseline: 1.2603x; 1.2603x over previous
#include <cuda_runtime.h>
#include <cuda_bf16.h>
#include <cstdint>

#define NN 8192
#define DIN 256
#define DOUT 32
#define NPART 256            // pool partial blocks (32 rows each)
#define NCHUNK 128

__device__ __align__(16) __nv_bfloat16 g_Bhi[DOUT * NN];
__device__ __align__(16) __nv_bfloat16 g_Blo[DOUT * NN];
__device__ float    g_logits[NN * DOUT];
__device__ unsigned g_colmax_bits[DOUT];
__device__ float    g_sumpart[NPART * DOUT];
__device__ float    g_part[NPART * DOUT * DIN];

// ---------------- helpers ----------------
__device__ __forceinline__ unsigned long long pack2(float x) {
    unsigned long long r; asm("mov.b64 %0, {%1, %1};" : "=l"(r) : "f"(x)); return r;
}
__device__ __forceinline__ unsigned long long ffma2(unsigned long long a,
                                                    unsigned long long b,
                                                    unsigned long long c) {
    unsigned long long d;
    asm("fma.rn.f32x2 %0, %1, %2, %3;" : "=l"(d) : "l"(a), "l"(b), "l"(c));
    return d;
}
__device__ __forceinline__ float2 unpack2(unsigned long long v) {
    float2 f; asm("mov.b64 {%0, %1}, %2;" : "=f"(f.x), "=f"(f.y) : "l"(v)); return f;
}
__device__ __forceinline__ unsigned fkey(float f) {
    int b = __float_as_int(f);
    return (unsigned)(b ^ ((b >> 31) | 0x80000000));
}
__device__ __forceinline__ float funkey(unsigned u) {
    int b = (u & 0x80000000u) ? (int)(u ^ 0x80000000u) : ~(int)u;
    return __int_as_float(b);
}
__device__ __forceinline__ void split2t(float2 v, uint32_t& hi, uint32_t& lo) {
    uint32_t u0 = __float_as_uint(v.x), u1 = __float_as_uint(v.y);
    asm("prmt.b32 %0, %1, %2, 0x7632;" : "=r"(hi) : "r"(u0), "r"(u1));
    float l0 = v.x - __uint_as_float(u0 & 0xFFFF0000u);
    float l1 = v.y - __uint_as_float(u1 & 0xFFFF0000u);
    asm("cvt.rn.bf16x2.f32 %0, %1, %2;" : "=r"(lo) : "f"(l1), "f"(l0));
}
__device__ __forceinline__ uint32_t smem_u32(const void* p) {
    uint32_t a;
    asm("{ .reg .u64 t; cvta.to.shared.u64 t, %1; cvt.u32.u64 %0, t; }"
        : "=r"(a) : "l"(p));
    return a;
}
__device__ __forceinline__ void mma_bf16(float& c0, float& c1, float& c2, float& c3,
                                         uint32_t a0, uint32_t a1, uint32_t a2,
                                         uint32_t a3, uint32_t b0, uint32_t b1) {
    asm volatile(
        "mma.sync.aligned.m16n8k16.row.col.f32.bf16.bf16.f32 "
        "{%0,%1,%2,%3}, {%4,%5,%6,%7}, {%8,%9}, {%0,%1,%2,%3};"
        : "+f"(c0), "+f"(c1), "+f"(c2), "+f"(c3)
        : "r"(a0), "r"(a1), "r"(a2), "r"(a3), "r"(b0), "r"(b1));
}
#define CP16(sm, gp) asm volatile( \
    "cp.async.cg.shared.global [%0], [%1], 16;" :: "r"(sm), "l"(gp) : "memory")
#define CP_COMMIT() asm volatile("cp.async.commit_group;" ::: "memory")
#define CP_WAIT4()  asm volatile("cp.async.wait_group 4;" ::: "memory")

// ---------------------------------------------------------------------------
// gemm2 (round-8 champion): 128 CTAs x 64 rows, 8 warps = 4 m16 x 2 K-halves,
// cp.async 6-deep ring, bf16 3-term with truncation split.
// ---------------------------------------------------------------------------
#define BUFW 7168
#define BHI_OFF 4608
#define BLO_OFF 5888
#define RING 6
#define GEMM2_SMEM (RING * BUFW * 4)     // 172032 B

__global__ void __launch_bounds__(256, 1)
gemm2_kernel(const float* __restrict__ A)
{
    extern __shared__ uint32_t smu[];
    __shared__ unsigned smax[DOUT];
    const int t = threadIdx.x;
    const int w = t >> 5, lane = t & 31;
    const int gid = lane >> 2, t4 = lane & 3;
    const int half = w >> 2, m0 = (w & 3) * 16;
    const int rb = blockIdx.x * 64;
    const uint32_t* __restrict__ BHg = (const uint32_t*)g_Bhi;
    const uint32_t* __restrict__ BLg = (const uint32_t*)g_Blo;
    const uint32_t smaddr = smem_u32(smu);

    if (t < DOUT) smax[t] = 0u;

    const float* gA[4]; uint32_t sA[4];
#pragma unroll
    for (int j = 0; j < 4; j++) {
        int f = t + j * 256;
        int hf = f >> 9, r = (f >> 3) & 63, seg = f & 7;
        gA[j] = A + (size_t)(rb + r) * NN + hf * 4096 + seg * 4;
        sA[j] = smaddr + 4u * (hf * 2304 + r * 36 + seg * 4);
    }
    const uint32_t* gB[2]; uint32_t sB[2];
#pragma unroll
    for (int j = 0; j < 2; j++) {
        int f = t + j * 256;
        int arr = f >> 8, rem = f & 255;
        int hs = rem >> 7, ns = (rem >> 2) & 31, sg = rem & 3;
        gB[j] = (arr ? BLg : BHg) + ns * 4096 + hs * 2048 + sg * 4;
        sB[j] = smaddr + 4u * ((arr ? BLO_OFF : BHI_OFF) + hs * 640 + ns * 20 + sg * 4);
    }

    float acc[4][4];
#pragma unroll
    for (int j = 0; j < 4; j++)
#pragma unroll
        for (int i = 0; i < 4; i++) acc[j][i] = 0.0f;

#pragma unroll
    for (int p = 0; p < 5; p++) {
        uint32_t bo = (uint32_t)p * (BUFW * 4);
#pragma unroll
        for (int j = 0; j < 4; j++) CP16(sA[j] + bo, gA[j] + p * 32);
#pragma unroll
        for (int j = 0; j < 2; j++) CP16(sB[j] + bo, gB[j] + p * 16);
        CP_COMMIT();
    }

    int bufc = 0, bufp = 5;
    for (int ch = 0; ch < NCHUNK; ch++) {
        CP_WAIT4();
        __syncthreads();
        if (ch + 5 < NCHUNK) {
            uint32_t bo = (uint32_t)bufp * (BUFW * 4);
            int ko = (ch + 5) * 32, kw = (ch + 5) * 16;
#pragma unroll
            for (int j = 0; j < 4; j++) CP16(sA[j] + bo, gA[j] + ko);
#pragma unroll
            for (int j = 0; j < 2; j++) CP16(sB[j] + bo, gB[j] + kw);
        }
        CP_COMMIT();
        if (++bufp == RING) bufp = 0;

        const uint32_t* sb = smu + bufc * BUFW;
        if (++bufc == RING) bufc = 0;
        const float* sbf = (const float*)sb;
#pragma unroll
        for (int s = 0; s < 2; s++) {
            const int ab = half * 2304 + s * 16 + 2 * t4;
            float2 v00 = *reinterpret_cast<const float2*>(sbf + ab + (m0 + gid) * 36);
            float2 v10 = *reinterpret_cast<const float2*>(sbf + ab + (m0 + gid + 8) * 36);
            float2 v01 = *reinterpret_cast<const float2*>(sbf + ab + 8 + (m0 + gid) * 36);
            float2 v11 = *reinterpret_cast<const float2*>(sbf + ab + 8 + (m0 + gid + 8) * 36);
            uint32_t ah0, ah1, ah2, ah3, al0, al1, al2, al3;
            split2t(v00, ah0, al0);
            split2t(v10, ah1, al1);
            split2t(v01, ah2, al2);
            split2t(v11, ah3, al3);
#pragma unroll
            for (int j = 0; j < 4; j++) {
                const int bx = BHI_OFF + half * 640 + (gid + 8 * j) * 20 + s * 8 + t4;
                uint32_t bh0 = sb[bx], bh1 = sb[bx + 4];
                uint32_t bl0 = sb[bx + (BLO_OFF - BHI_OFF)];
                uint32_t bl1 = sb[bx + (BLO_OFF - BHI_OFF) + 4];
                mma_bf16(acc[j][0], acc[j][1], acc[j][2], acc[j][3],
                         ah0, ah1, ah2, ah3, bh0, bh1);
                mma_bf16(acc[j][0], acc[j][1], acc[j][2], acc[j][3],
                         ah0, ah1, ah2, ah3, bl0, bl1);
                mma_bf16(acc[j][0], acc[j][1], acc[j][2], acc[j][3],
                         al0, al1, al2, al3, bh0, bh1);
            }
        }
    }
    __syncthreads();

    float* red = (float*)smu;   // overlay [64][33]
    if (half == 1) {
#pragma unroll
        for (int j = 0; j < 4; j++) {
            int r0 = m0 + gid, c = 8 * j + 2 * t4;
            red[r0 * 33 + c]           = acc[j][0];
            red[r0 * 33 + c + 1]       = acc[j][1];
            red[(r0 + 8) * 33 + c]     = acc[j][2];
            red[(r0 + 8) * 33 + c + 1] = acc[j][3];
        }
    }
    __syncthreads();
    if (half == 0) {
#pragma unroll
        for (int j = 0; j < 4; j++) {
            int r0 = m0 + gid, c = 8 * j + 2 * t4;
            float v0 = acc[j][0] + red[r0 * 33 + c];
            float v1 = acc[j][1] + red[r0 * 33 + c + 1];
            float v2 = acc[j][2] + red[(r0 + 8) * 33 + c];
            float v3 = acc[j][3] + red[(r0 + 8) * 33 + c + 1];
            *reinterpret_cast<float2*>(&g_logits[(size_t)(rb + r0) * DOUT + c]) =
                make_float2(v0, v1);
            *reinterpret_cast<float2*>(&g_logits[(size_t)(rb + r0 + 8) * DOUT + c]) =
                make_float2(v2, v3);
            atomicMax(&smax[c],     fkey(fmaxf(v0, v2)));
            atomicMax(&smax[c + 1], fkey(fmaxf(v1, v3)));
        }
    }
    __syncthreads();
    if (t < DOUT) atomicMax(&g_colmax_bits[t], smax[t]);
}

// ---------------------------------------------------------------------------
// gemm1: support = X @ W -> pre-split, pre-transposed bf16 hi/lo.
// ---------------------------------------------------------------------------
#define ABUF_STRIDE (32 * 65)
#define SBUF_BASE   (8 * ABUF_STRIDE)
#define GEMM1_SMEM  ((SBUF_BASE + 8 * 32 * 32) * 4)

__global__ void __launch_bounds__(256)
gemm1_kernel(const float* __restrict__ A, const float* __restrict__ S)
{
    extern __shared__ float smem[];
    const int t = threadIdx.x, w = t >> 5, l = t & 31;
    const int rb = blockIdx.x * 64;
    const int K = DIN;

    if (blockIdx.x == 0 && t < DOUT) g_colmax_bits[t] = 0u;

    float* a_buf = smem + w * ABUF_STRIDE;
    float* s_buf = smem + SBUF_BASE + w * (32 * 32);
    const int kc = w * 32;

    unsigned long long acc0[16], acc1[16];
#pragma unroll
    for (int i = 0; i < 16; i++) { acc0[i] = 0ull; acc1[i] = 0ull; }

#pragma unroll
    for (int j = 0; j < 16; j++) {
        int f = j * 32 + l, row = f >> 3, k4 = (f & 7) << 2;
        float4 v = *reinterpret_cast<const float4*>(
            A + (size_t)(rb + row) * K + kc + k4);
        a_buf[(k4 + 0) * 65 + row] = v.x;
        a_buf[(k4 + 1) * 65 + row] = v.y;
        a_buf[(k4 + 2) * 65 + row] = v.z;
        a_buf[(k4 + 3) * 65 + row] = v.w;
    }
#pragma unroll
    for (int j = 0; j < 8; j++) {
        int f = j * 32 + l;
        *reinterpret_cast<float4*>(s_buf + f * 4) =
            *reinterpret_cast<const float4*>(S + (size_t)kc * 32 + f * 4);
    }
    __syncwarp();
#pragma unroll 4
    for (int k = 0; k < 32; k++) {
        unsigned long long a0 = pack2(a_buf[k * 65 + l]);
        unsigned long long a1 = pack2(a_buf[k * 65 + l + 32]);
        const ulonglong2* s2 = reinterpret_cast<const ulonglong2*>(s_buf + k * 32);
#pragma unroll
        for (int c = 0; c < 8; c++) {
            ulonglong2 sv = s2[c];
            acc0[2 * c]     = ffma2(a0, sv.x, acc0[2 * c]);
            acc0[2 * c + 1] = ffma2(a0, sv.y, acc0[2 * c + 1]);
            acc1[2 * c]     = ffma2(a1, sv.x, acc1[2 * c]);
            acc1[2 * c + 1] = ffma2(a1, sv.y, acc1[2 * c + 1]);
        }
    }

    __syncthreads();
    float* red = smem;
#pragma unroll
    for (int c = 0; c < 16; c++) {
        float2 v0 = unpack2(acc0[c]);
        float2 v1 = unpack2(acc1[c]);
        red[(w * 64 + l) * 33 + 2 * c]          = v0.x;
        red[(w * 64 + l) * 33 + 2 * c + 1]      = v0.y;
        red[(w * 64 + l + 32) * 33 + 2 * c]     = v1.x;
        red[(w * 64 + l + 32) * 33 + 2 * c + 1] = v1.y;
    }
    __syncthreads();
    {
        int row = t >> 2, c0 = (t & 3) * 8;
        float r[8];
#pragma unroll
        for (int i = 0; i < 8; i++) r[i] = 0.0f;
#pragma unroll
        for (int ww = 0; ww < 8; ww++) {
            const float* p = red + (ww * 64 + row) * 33 + c0;
#pragma unroll
            for (int i = 0; i < 8; i++) r[i] += p[i];
        }
#pragma unroll
        for (int i = 0; i < 8; i++) {
            __nv_bfloat16 hi = __float2bfloat16(r[i]);
            g_Bhi[(size_t)(c0 + i) * NN + rb + row] = hi;
            g_Blo[(size_t)(c0 + i) * NN + rb + row] =
                __float2bfloat16(r[i] - __bfloat162float(hi));
        }
    }
}

// ---------------- pool: 32-row x d-split, fused per-block exp sums ---------
__global__ void __launch_bounds__(128, 4)
pool_kernel(const float* __restrict__ X)
{
    __shared__ float wsm[32 * DOUT];
    __shared__ float cmax[DOUT];
    const int t   = threadIdx.x;              // 128
    const int blk = (int)blockIdx.x >> 1;     // 0..255
    const int dh  = (int)blockIdx.x & 1;
    const int rb  = blk * 32;
    const int d   = dh * 128 + t;

    if (t < DOUT) cmax[t] = funkey(g_colmax_bits[t]);
    __syncthreads();
#pragma unroll
    for (int q = 0; q < 8; q++) {
        int idx = t * 8 + q, il = idx >> 5, c = idx & 31;
        wsm[idx] = __expf(g_logits[(size_t)(rb + il) * DOUT + c] - cmax[c]);
    }
    __syncthreads();

    // fused expsum partial (conflict-free column sums; only dh==0 writes)
    if (dh == 0 && t < DOUT) {
        float s = 0.f;
#pragma unroll 8
        for (int il = 0; il < 32; il++) s += wsm[il * DOUT + t];
        g_sumpart[blk * DOUT + t] = s;
    }

    unsigned long long acc[16];
#pragma unroll
    for (int i = 0; i < 16; i++) acc[i] = 0ull;
    for (int g = 0; g < 4; g++) {
        float xv[8];
#pragma unroll
        for (int q = 0; q < 8; q++)
            xv[q] = X[(size_t)(rb + g * 8 + q) * DIN + d];
#pragma unroll
        for (int q = 0; q < 8; q++) {
            unsigned long long xp = pack2(xv[q]);
            const ulonglong2* wv =
                reinterpret_cast<const ulonglong2*>(wsm + (g * 8 + q) * DOUT);
#pragma unroll
            for (int c = 0; c < 8; c++) {
                ulonglong2 sv = wv[c];
                acc[2 * c]     = ffma2(xp, sv.x, acc[2 * c]);
                acc[2 * c + 1] = ffma2(xp, sv.y, acc[2 * c + 1]);
            }
        }
    }
    float* pp = g_part + (size_t)blk * (DOUT * DIN);
#pragma unroll
    for (int c = 0; c < 16; c++) {
        float2 v = unpack2(acc[c]);
        pp[(2 * c) * DIN + d]     = v.x;
        pp[(2 * c + 1) * DIN + d] = v.y;
    }
}

// ---------------------------------------------------------------------------
// reduce_out: 256 CTAs = 32 cols x 8 d-slices of 32. Each CTA: 8 sub-sums of
// 32 partials (coalesced 128B lines) + fixed-order 8-way merge -> determin.
// ---------------------------------------------------------------------------
__global__ void __launch_bounds__(256, 4)
reduce_out_kernel(float* __restrict__ out)
{
    __shared__ float s1[128];
    __shared__ float red2[8 * 32];
    const int c  = (int)blockIdx.x >> 3;
    const int d0 = ((int)blockIdx.x & 7) * 32;
    const int t  = threadIdx.x;

    // inv[c]: fixed-order pair + tree reduce of 256 sumpart entries
    if (t < 128)
        s1[t] = g_sumpart[t * DOUT + c] + g_sumpart[(t + 128) * DOUT + c];
    __syncthreads();
    for (int s = 64; s > 0; s >>= 1) {
        if (t < s) s1[t] += s1[t + s];
        __syncthreads();
    }
    const float inv = 1.0f / s1[0];

    // 8 sub-sums over fixed partial sets (sub gets b = sub + 8*i)
    const int sub = t >> 5, j = t & 31;
    float s = 0.0f;
    const float* base = g_part + (size_t)c * DIN + d0 + j;
#pragma unroll 8
    for (int i = 0; i < 32; i++)
        s += base[(size_t)(sub + 8 * i) * (DOUT * DIN)];
    red2[sub * 32 + j] = s;
    __syncthreads();
    if (t < 32) {
        float r = 0.0f;
#pragma unroll
        for (int q = 0; q < 8; q++) r += red2[q * 32 + t];
        out[c * DIN + d0 + t] = r * inv;
    }
}

extern "C" void kernel_launch(void* const* d_in, const int* in_sizes, int n_in,
                              void* d_out, int out_size)
{
    const float* X = (const float*)d_in[0];
    const float* A = (const float*)d_in[1];
    const float* W = (const float*)d_in[2];
    // d_in[3] = b: per-column constant -> softmax(axis 0) invariant -> dropped
    float* out = (float*)d_out;

    cudaFuncSetAttribute(gemm1_kernel,
                         cudaFuncAttributeMaxDynamicSharedMemorySize, GEMM1_SMEM);
    cudaFuncSetAttribute(gemm2_kernel,
                         cudaFuncAttributeMaxDynamicSharedMemorySize, GEMM2_SMEM);

    gemm1_kernel<<<NN / 64, 256, GEMM1_SMEM>>>(X, W);
    gemm2_kernel<<<NN / 64, 256, GEMM2_SMEM>>>(A);
    pool_kernel<<<NPART * 2, 128>>>(X);
    reduce_out_kernel<<<DOUT * 8, 256>>>(out);
}